// round 2
// baseline (speedup 1.0000x reference)
#include <cuda_runtime.h>
#include <math.h>

#define BATCH 4
#define CH    128
#define NTOK  4096   // 64*64
#define TQ    64
#define TK    64
#define QTILES (NTOK / TQ)           // 64
#define NBLK   (BATCH * QTILES)      // 256

// Scratch for Q, K, V in token-major layout [b][n][c] (contiguous rows of 128 floats).
__device__ float g_Q[BATCH * NTOK * CH];
__device__ float g_K[BATCH * NTOK * CH];
__device__ float g_V[BATCH * NTOK * CH];

// ---------------------------------------------------------------------------
// Kernel 1: QKV projections. y[t,co] = sum_c in[t,c] * W[co,c] + bias[co]
// blockIdx.y selects which projection (0=Q from prompt, 1=K from x, 2=V from x).
// Block handles 64 tokens x 128 outputs, 256 threads, 4x8 register microtile.
// ---------------------------------------------------------------------------
__global__ __launch_bounds__(256, 1)
void qkv_kernel(const float* __restrict__ prompt, const float* __restrict__ x,
                const float* __restrict__ Wq, const float* __restrict__ bq,
                const float* __restrict__ Wk, const float* __restrict__ bk,
                const float* __restrict__ Wv, const float* __restrict__ bv)
{
    extern __shared__ float sm[];
    float* Xs = sm;             // 64 x 132 (token-major input tile, padded)
    float* Wt = sm + 64 * 132;  // 128 x 132 (W transposed: Wt[c][co])

    const int which = blockIdx.y;
    const float* in   = (which == 0) ? prompt : x;
    const float* W    = (which == 0) ? Wq : (which == 1) ? Wk : Wv;
    const float* bias = (which == 0) ? bq : (which == 1) ? bk : bv;
    float* outg       = (which == 0) ? g_Q : (which == 1) ? g_K : g_V;

    const int b  = blockIdx.x >> 6;         // blockIdx.x / 64
    const int nb = (blockIdx.x & 63) * 64;  // token tile base
    const int tid = threadIdx.x;

    // Load input tile, transposing (b,c,n) -> Xs[t][c]. Coalesced on n.
    for (int idx = tid; idx < 64 * CH; idx += 256) {
        int t = idx & 63, c = idx >> 6;
        Xs[t * 132 + c] = in[((size_t)b * CH + c) * NTOK + nb + t];
    }
    // Load W transposed: Wt[c][co] = W[co][c]. Coalesced on c.
    for (int idx = tid; idx < CH * CH; idx += 256) {
        int c = idx & 127, co = idx >> 7;
        Wt[c * 132 + co] = W[co * CH + c];
    }
    __syncthreads();

    const int tx = tid & 15, ty = tid >> 4;
    float4 ba = *(const float4*)&bias[tx * 4];
    float4 bb = *(const float4*)&bias[64 + tx * 4];
    float acc[4][8];
    #pragma unroll
    for (int i = 0; i < 4; i++) {
        acc[i][0] = ba.x; acc[i][1] = ba.y; acc[i][2] = ba.z; acc[i][3] = ba.w;
        acc[i][4] = bb.x; acc[i][5] = bb.y; acc[i][6] = bb.z; acc[i][7] = bb.w;
    }

    #pragma unroll 4
    for (int c = 0; c < CH; c++) {
        float4 wa = *(float4*)&Wt[c * 132 + tx * 4];
        float4 wb = *(float4*)&Wt[c * 132 + 64 + tx * 4];
        #pragma unroll
        for (int i = 0; i < 4; i++) {
            float xv = Xs[(ty * 4 + i) * 132 + c];
            acc[i][0] += xv * wa.x; acc[i][1] += xv * wa.y;
            acc[i][2] += xv * wa.z; acc[i][3] += xv * wa.w;
            acc[i][4] += xv * wb.x; acc[i][5] += xv * wb.y;
            acc[i][6] += xv * wb.z; acc[i][7] += xv * wb.w;
        }
    }

    #pragma unroll
    for (int i = 0; i < 4; i++) {
        int n = nb + ty * 4 + i;
        float* orow = &outg[(size_t)(b * NTOK + n) * CH];
        *(float4*)&orow[tx * 4]      = make_float4(acc[i][0], acc[i][1], acc[i][2], acc[i][3]);
        *(float4*)&orow[64 + tx * 4] = make_float4(acc[i][4], acc[i][5], acc[i][6], acc[i][7]);
    }
}

// ---------------------------------------------------------------------------
// Kernel 2: fused masked flash-attention + residual + LayerNorm.
// One block = 64 query tokens of one batch. Online softmax over 64 key tiles.
// 256 threads as 16x16. Score stage: 4 rows x 4 cols (cols m = tx + 16j).
// Output stage: 4 rows x 8 channels (cols co = tx*4+j and 64+tx*4+j).
// ---------------------------------------------------------------------------
__global__ __launch_bounds__(256, 1)
void attn_kernel(const float* __restrict__ x, const int* __restrict__ mask,
                 const float* __restrict__ gamma, const float* __restrict__ beta,
                 float* __restrict__ out)
{
    extern __shared__ float sm[];
    float* Qs   = sm;               // 64 x 132
    float* Ks   = Qs + 64 * 132;    // 64 x 132
    float* Vs   = Ks + 64 * 132;    // 64 x 132
    float* Ss   = Vs + 64 * 132;    // 64 x 66 (probabilities)
    float* m_s  = Ss + 64 * 66;     // 64 running max
    float* l_s  = m_s + 64;         // 64 running sum
    float* sc_s = l_s + 64;         // 64 rescale factors
    float* mk_s = sc_s + 64;        // 64 additive mask for current key tile

    const int b  = blockIdx.x >> 6;
    const int qb = (blockIdx.x & 63) * 64;
    const int tid = threadIdx.x;
    const int tx = tid & 15, ty = tid >> 4;
    const float qscale = 0.0883883476483184f; // 1/sqrt(128)

    // Load Q tile, pre-scaled by 1/sqrt(C).
    const float4* Qrow = (const float4*)&g_Q[(size_t)(b * NTOK + qb) * CH];
    for (int idx = tid; idx < 64 * 32; idx += 256) {
        int t = idx >> 5, c4 = idx & 31;
        float4 v = Qrow[t * 32 + c4];
        v.x *= qscale; v.y *= qscale; v.z *= qscale; v.w *= qscale;
        *(float4*)&Qs[t * 132 + c4 * 4] = v;
    }
    if (tid < 64) { m_s[tid] = -INFINITY; l_s[tid] = 0.f; }

    float o[4][8];
    #pragma unroll
    for (int i = 0; i < 4; i++)
        #pragma unroll
        for (int j = 0; j < 8; j++) o[i][j] = 0.f;

    for (int kt = 0; kt < NTOK / TK; kt++) {
        __syncthreads();  // previous O-stage done reading Vs/Ss
        const int kb = kt * 64;
        const float4* Kr = (const float4*)&g_K[(size_t)(b * NTOK + kb) * CH];
        const float4* Vr = (const float4*)&g_V[(size_t)(b * NTOK + kb) * CH];
        for (int idx = tid; idx < 64 * 32; idx += 256) {
            int t = idx >> 5, c4 = idx & 31;
            *(float4*)&Ks[t * 132 + c4 * 4] = Kr[t * 32 + c4];
            *(float4*)&Vs[t * 132 + c4 * 4] = Vr[t * 32 + c4];
        }
        if (tid < 64)
            mk_s[tid] = (mask[b * NTOK + kb + tid] > 0) ? 0.f : -1e30f;
        __syncthreads();

        // --- scores S = Q K^T (rows ty*4+i, cols tx+16j) ---
        float s[4][4];
        #pragma unroll
        for (int i = 0; i < 4; i++)
            #pragma unroll
            for (int j = 0; j < 4; j++) s[i][j] = 0.f;

        #pragma unroll 2
        for (int c4 = 0; c4 < 32; c4++) {
            float4 q[4], k[4];
            #pragma unroll
            for (int i = 0; i < 4; i++)
                q[i] = *(float4*)&Qs[(ty * 4 + i) * 132 + c4 * 4];
            #pragma unroll
            for (int j = 0; j < 4; j++)
                k[j] = *(float4*)&Ks[(tx + j * 16) * 132 + c4 * 4];
            #pragma unroll
            for (int i = 0; i < 4; i++)
                #pragma unroll
                for (int j = 0; j < 4; j++)
                    s[i][j] += q[i].x * k[j].x + q[i].y * k[j].y
                             + q[i].z * k[j].z + q[i].w * k[j].w;
        }
        #pragma unroll
        for (int j = 0; j < 4; j++) {
            float ma = mk_s[tx + j * 16];
            #pragma unroll
            for (int i = 0; i < 4; i++) s[i][j] += ma;
        }

        // --- online softmax update, row-owned by a 16-lane group ---
        #pragma unroll
        for (int i = 0; i < 4; i++) {
            int r = ty * 4 + i;
            float tm = fmaxf(fmaxf(s[i][0], s[i][1]), fmaxf(s[i][2], s[i][3]));
            #pragma unroll
            for (int off = 8; off >= 1; off >>= 1)
                tm = fmaxf(tm, __shfl_xor_sync(0xffffffffu, tm, off, 16));
            float mold = m_s[r];
            float mnew = fmaxf(mold, tm);
            float rs = 0.f;
            #pragma unroll
            for (int j = 0; j < 4; j++) {
                float p = __expf(s[i][j] - mnew);
                s[i][j] = p; rs += p;
            }
            #pragma unroll
            for (int off = 8; off >= 1; off >>= 1)
                rs += __shfl_xor_sync(0xffffffffu, rs, off, 16);
            if (tx == 0) {
                float scl = __expf(mold - mnew);
                sc_s[r] = scl;
                l_s[r]  = l_s[r] * scl + rs;
                m_s[r]  = mnew;
            }
            #pragma unroll
            for (int j = 0; j < 4; j++)
                Ss[r * 66 + tx + j * 16] = s[i][j];
        }
        __syncthreads();

        // --- rescale accumulator, then O += P @ V ---
        #pragma unroll
        for (int i = 0; i < 4; i++) {
            float f = sc_s[ty * 4 + i];
            #pragma unroll
            for (int j = 0; j < 8; j++) o[i][j] *= f;
        }
        #pragma unroll 2
        for (int k = 0; k < 64; k++) {
            float4 va = *(float4*)&Vs[k * 132 + tx * 4];
            float4 vb = *(float4*)&Vs[k * 132 + 64 + tx * 4];
            #pragma unroll
            for (int i = 0; i < 4; i++) {
                float p = Ss[(ty * 4 + i) * 66 + k];
                o[i][0] += p * va.x; o[i][1] += p * va.y;
                o[i][2] += p * va.z; o[i][3] += p * va.w;
                o[i][4] += p * vb.x; o[i][5] += p * vb.y;
                o[i][6] += p * vb.z; o[i][7] += p * vb.w;
            }
        }
    }
    __syncthreads();  // final l_s visible to all lanes

    // --- epilogue: normalize, residual, LayerNorm over channels, write out ---
    float g[8], be[8];
    #pragma unroll
    for (int j = 0; j < 8; j++) {
        int co = (j < 4) ? tx * 4 + j : 64 + tx * 4 + (j - 4);
        g[j] = gamma[co]; be[j] = beta[co];
    }
    #pragma unroll
    for (int i = 0; i < 4; i++) {
        int r = ty * 4 + i;
        int n = qb + r;
        float invl = 1.f / l_s[r];
        float v[8], sum = 0.f, sq = 0.f;
        #pragma unroll
        for (int j = 0; j < 8; j++) {
            int co = (j < 4) ? tx * 4 + j : 64 + tx * 4 + (j - 4);
            float val = o[i][j] * invl + x[((size_t)b * CH + co) * NTOK + n];
            v[j] = val; sum += val; sq += val * val;
        }
        #pragma unroll
        for (int off = 8; off >= 1; off >>= 1) {
            sum += __shfl_xor_sync(0xffffffffu, sum, off, 16);
            sq  += __shfl_xor_sync(0xffffffffu, sq,  off, 16);
        }
        float mu   = sum * (1.f / 128.f);
        float var  = sq  * (1.f / 128.f) - mu * mu;
        float rstd = rsqrtf(var + 1e-5f);
        #pragma unroll
        for (int j = 0; j < 8; j++) {
            int co = (j < 4) ? tx * 4 + j : 64 + tx * 4 + (j - 4);
            out[((size_t)b * CH + co) * NTOK + n] = (v[j] - mu) * rstd * g[j] + be[j];
        }
    }
}

// ---------------------------------------------------------------------------
extern "C" void kernel_launch(void* const* d_in, const int* in_sizes, int n_in,
                              void* d_out, int out_size)
{
    const float* prompt = (const float*)d_in[0];
    const float* x      = (const float*)d_in[1];
    const float* Wq     = (const float*)d_in[2];
    const float* bq     = (const float*)d_in[3];
    const float* Wk     = (const float*)d_in[4];
    const float* bk     = (const float*)d_in[5];
    const float* Wv     = (const float*)d_in[6];
    const float* bv     = (const float*)d_in[7];
    const float* gamma  = (const float*)d_in[8];
    const float* beta   = (const float*)d_in[9];
    const int*   mask   = (const int*)d_in[10];
    float* out = (float*)d_out;

    const int qkv_smem  = (64 * 132 + 128 * 132) * (int)sizeof(float);   // 101376
    const int attn_smem = (3 * 64 * 132 + 64 * 66 + 4 * 64) * (int)sizeof(float); // 119296

    // Idempotent attribute sets (no static guards; safe during graph capture).
    cudaFuncSetAttribute(qkv_kernel,  cudaFuncAttributeMaxDynamicSharedMemorySize, qkv_smem);
    cudaFuncSetAttribute(attn_kernel, cudaFuncAttributeMaxDynamicSharedMemorySize, attn_smem);

    dim3 grid_qkv(NBLK, 3);
    qkv_kernel<<<grid_qkv, 256, qkv_smem>>>(prompt, x, Wq, bq, Wk, bk, Wv, bv);
    attn_kernel<<<NBLK, 256, attn_smem>>>(x, mask, gamma, beta, out);
}

// round 4
// speedup vs baseline: 6.3924x; 6.3924x over previous
#include <cuda_runtime.h>
#include <cuda_fp16.h>
#include <math.h>

#define BATCH 4
#define CH    128
#define NTOK  4096
#define TQ    128
#define TK    64
#define QP    136   // Q/K/V smem pitch (halves); 272B, %128==16 -> ldmatrix conflict-free
#define PP    72    // P smem pitch (halves); 144B, %128==16

// fp16 staging buffers written by qkv kernel (Q pre-scaled by 1/sqrt(C)).
__device__ __half g_Q[BATCH * NTOK * CH];
__device__ __half g_K[BATCH * NTOK * CH];
__device__ __half g_V[BATCH * NTOK * CH];

// ---------------------------------------------------------------------------
// PTX helpers
// ---------------------------------------------------------------------------
__device__ __forceinline__ unsigned smem_u32(const void* p) {
    return (unsigned)__cvta_generic_to_shared(p);
}
__device__ __forceinline__ void cp16(unsigned dst, const void* src) {
    asm volatile("cp.async.cg.shared.global [%0], [%1], 16;\n" :: "r"(dst), "l"(src));
}
__device__ __forceinline__ void cp_commit() {
    asm volatile("cp.async.commit_group;\n");
}
template<int N> __device__ __forceinline__ void cp_wait() {
    asm volatile("cp.async.wait_group %0;\n" :: "n"(N));
}
__device__ __forceinline__ void ldsm4(unsigned addr, unsigned& a0, unsigned& a1,
                                      unsigned& a2, unsigned& a3) {
    asm volatile("ldmatrix.sync.aligned.m8n8.x4.shared.b16 {%0,%1,%2,%3}, [%4];\n"
                 : "=r"(a0), "=r"(a1), "=r"(a2), "=r"(a3) : "r"(addr));
}
__device__ __forceinline__ void ldsm2(unsigned addr, unsigned& b0, unsigned& b1) {
    asm volatile("ldmatrix.sync.aligned.m8n8.x2.shared.b16 {%0,%1}, [%2];\n"
                 : "=r"(b0), "=r"(b1) : "r"(addr));
}
__device__ __forceinline__ void ldsm2t(unsigned addr, unsigned& b0, unsigned& b1) {
    asm volatile("ldmatrix.sync.aligned.m8n8.x2.trans.shared.b16 {%0,%1}, [%2];\n"
                 : "=r"(b0), "=r"(b1) : "r"(addr));
}
__device__ __forceinline__ void mma16816(float& d0, float& d1, float& d2, float& d3,
                                         unsigned a0, unsigned a1, unsigned a2, unsigned a3,
                                         unsigned b0, unsigned b1) {
    asm volatile("mma.sync.aligned.m16n8k16.row.col.f32.f16.f16.f32 "
                 "{%0,%1,%2,%3}, {%4,%5,%6,%7}, {%8,%9}, {%0,%1,%2,%3};\n"
                 : "+f"(d0), "+f"(d1), "+f"(d2), "+f"(d3)
                 : "r"(a0), "r"(a1), "r"(a2), "r"(a3), "r"(b0), "r"(b1));
}

// ---------------------------------------------------------------------------
// Kernel 1: QKV projections (SIMT fp32 math, fp16 output; Q pre-scaled).
// ---------------------------------------------------------------------------
__global__ __launch_bounds__(256, 1)
void qkv_kernel(const float* __restrict__ prompt, const float* __restrict__ x,
                const float* __restrict__ Wq, const float* __restrict__ bq,
                const float* __restrict__ Wk, const float* __restrict__ bk,
                const float* __restrict__ Wv, const float* __restrict__ bv)
{
    extern __shared__ char smraw[];
    float* Xs = (float*)smraw;        // 64 x 132
    float* Wt = Xs + 64 * 132;        // 128 x 132

    const int which = blockIdx.y;
    const float* in   = (which == 0) ? prompt : x;
    const float* W    = (which == 0) ? Wq : (which == 1) ? Wk : Wv;
    const float* bias = (which == 0) ? bq : (which == 1) ? bk : bv;
    __half* outg      = (which == 0) ? g_Q : (which == 1) ? g_K : g_V;
    const float oscale = (which == 0) ? 0.0883883476483184f : 1.0f;  // 1/sqrt(128)

    const int b  = blockIdx.x >> 6;
    const int nb = (blockIdx.x & 63) * 64;
    const int tid = threadIdx.x;

    for (int idx = tid; idx < 64 * CH; idx += 256) {
        int t = idx & 63, c = idx >> 6;
        Xs[t * 132 + c] = in[((size_t)b * CH + c) * NTOK + nb + t];
    }
    for (int idx = tid; idx < CH * CH; idx += 256) {
        int c = idx & 127, co = idx >> 7;
        Wt[c * 132 + co] = W[co * CH + c];
    }
    __syncthreads();

    const int tx = tid & 15, ty = tid >> 4;
    float4 ba = *(const float4*)&bias[tx * 4];
    float4 bb = *(const float4*)&bias[64 + tx * 4];
    float acc[4][8];
    #pragma unroll
    for (int i = 0; i < 4; i++) {
        acc[i][0] = ba.x; acc[i][1] = ba.y; acc[i][2] = ba.z; acc[i][3] = ba.w;
        acc[i][4] = bb.x; acc[i][5] = bb.y; acc[i][6] = bb.z; acc[i][7] = bb.w;
    }

    #pragma unroll 4
    for (int c = 0; c < CH; c++) {
        float4 wa = *(float4*)&Wt[c * 132 + tx * 4];
        float4 wb = *(float4*)&Wt[c * 132 + 64 + tx * 4];
        #pragma unroll
        for (int i = 0; i < 4; i++) {
            float xv = Xs[(ty * 4 + i) * 132 + c];
            acc[i][0] += xv * wa.x; acc[i][1] += xv * wa.y;
            acc[i][2] += xv * wa.z; acc[i][3] += xv * wa.w;
            acc[i][4] += xv * wb.x; acc[i][5] += xv * wb.y;
            acc[i][6] += xv * wb.z; acc[i][7] += xv * wb.w;
        }
    }

    #pragma unroll
    for (int i = 0; i < 4; i++) {
        __half* orow = &outg[(size_t)(b * NTOK + nb + ty * 4 + i) * CH];
        *(__half2*)&orow[tx * 4]          = __floats2half2_rn(acc[i][0] * oscale, acc[i][1] * oscale);
        *(__half2*)&orow[tx * 4 + 2]      = __floats2half2_rn(acc[i][2] * oscale, acc[i][3] * oscale);
        *(__half2*)&orow[64 + tx * 4]     = __floats2half2_rn(acc[i][4] * oscale, acc[i][5] * oscale);
        *(__half2*)&orow[64 + tx * 4 + 2] = __floats2half2_rn(acc[i][6] * oscale, acc[i][7] * oscale);
    }
}

// ---------------------------------------------------------------------------
// Kernel 2: fp16 tensor-core flash attention + residual + LayerNorm.
// Block = 128 queries. 8 warps, warp = 16 query rows x all 64 key cols.
// K/V double-buffered via cp.async. Softmax fully warp-local.
// ---------------------------------------------------------------------------
#define SMEM_Q   0
#define SMEM_K   34816            // 2 bufs x 64*136*2
#define SMEM_V   69632
#define SMEM_P   104448           // 128*72*2
#define SMEM_MK  122880           // 4096 floats
#define SMEM_GB  139264           // gamma, beta
#define SMEM_TOT 140288
#define KVBUF    (TK * QP * 2)    // 17408 bytes

__global__ __launch_bounds__(256, 1)
void attn_kernel(const float* __restrict__ x, const int* __restrict__ mask,
                 const float* __restrict__ gamma, const float* __restrict__ beta,
                 float* __restrict__ out)
{
    extern __shared__ char smraw[];
    char* sm = smraw;
    __half* Qh  = (__half*)(sm + SMEM_Q);
    __half* Kh  = (__half*)(sm + SMEM_K);
    __half* Vh  = (__half*)(sm + SMEM_V);
    __half* Ph  = (__half*)(sm + SMEM_P);
    float*  mk  = (float*)(sm + SMEM_MK);
    float*  gms = (float*)(sm + SMEM_GB);
    float*  bts = gms + 128;

    const int tid = threadIdx.x, lane = tid & 31, wid = tid >> 5;
    const int b  = blockIdx.x >> 5;
    const int qb = (blockIdx.x & 31) * TQ;
    const int r0 = wid * 16;
    const int g  = lane >> 2, qd = lane & 3;

    // --- prologue loads ---
    for (int i = tid; i < 2048; i += 256) {           // Q tile: 128 rows x 256B
        int row = i >> 4, c8 = (i & 15) * 8;
        *(uint4*)(Qh + row * QP + c8) =
            *(const uint4*)(g_Q + ((size_t)(b * NTOK + qb + row)) * CH + c8);
    }
    for (int i = tid; i < NTOK; i += 256)
        mk[i] = (mask[b * NTOK + i] > 0) ? 0.0f : -1e30f;
    if (tid < 128) { gms[tid] = gamma[tid]; bts[tid] = beta[tid]; }

    // issue K/V tile 0
    {
        const __half* Ksrc = g_K + ((size_t)(b * NTOK)) * CH;
        const __half* Vsrc = g_V + ((size_t)(b * NTOK)) * CH;
        for (int i = tid; i < 1024; i += 256) {
            int row = i >> 4, c8 = (i & 15) * 8;
            cp16(smem_u32(Kh + row * QP + c8), Ksrc + row * CH + c8);
            cp16(smem_u32(Vh + row * QP + c8), Vsrc + row * CH + c8);
        }
        cp_commit();
    }

    // ldmatrix base addresses (byte addresses into shared)
    const unsigned aQ = smem_u32(Qh) + ((r0 + (lane & 15)) * QP + ((lane >> 4) * 8)) * 2;
    const unsigned aP = smem_u32(Ph) + ((r0 + (lane & 15)) * PP + ((lane >> 4) * 8)) * 2;
    const unsigned aK = smem_u32(Kh) + (((lane & 7) * QP) + (((lane & 15) >> 3) * 8)) * 2;
    const unsigned aV = smem_u32(Vh) + ((lane & 15) * QP) * 2;

    float m_A = -INFINITY, m_B = -INFINITY, l_A = 0.f, l_B = 0.f;
    float o[16][4];
    #pragma unroll
    for (int i = 0; i < 16; i++) { o[i][0] = o[i][1] = o[i][2] = o[i][3] = 0.f; }

    for (int kt = 0; kt < NTOK / TK; kt++) {
        // prefetch next tile
        if (kt < NTOK / TK - 1) {
            int nbuf = (kt + 1) & 1;
            const __half* Ksrc = g_K + ((size_t)(b * NTOK + (kt + 1) * TK)) * CH;
            const __half* Vsrc = g_V + ((size_t)(b * NTOK + (kt + 1) * TK)) * CH;
            for (int i = tid; i < 1024; i += 256) {
                int row = i >> 4, c8 = (i & 15) * 8;
                cp16(smem_u32(Kh + nbuf * (TK * QP) + row * QP + c8), Ksrc + row * CH + c8);
                cp16(smem_u32(Vh + nbuf * (TK * QP) + row * QP + c8), Vsrc + row * CH + c8);
            }
            cp_commit();
            cp_wait<1>();
        } else {
            cp_wait<0>();
        }
        __syncthreads();

        const unsigned kOff = (kt & 1) * KVBUF;

        // ---- scores S = Q K^T : warp computes 16 x 64 ----
        float c[8][4];
        #pragma unroll
        for (int nt = 0; nt < 8; nt++) { c[nt][0] = c[nt][1] = c[nt][2] = c[nt][3] = 0.f; }

        #pragma unroll
        for (int ks = 0; ks < 8; ks++) {
            unsigned a0, a1, a2, a3;
            ldsm4(aQ + ks * 32, a0, a1, a2, a3);
            #pragma unroll
            for (int nt = 0; nt < 8; nt++) {
                unsigned b0, b1;
                ldsm2(aK + kOff + nt * (8 * QP * 2) + ks * 32, b0, b1);
                mma16816(c[nt][0], c[nt][1], c[nt][2], c[nt][3], a0, a1, a2, a3, b0, b1);
            }
        }

        // ---- mask + warp-local online softmax ----
        const float* mkt = mk + kt * TK;
        float rmA = -INFINITY, rmB = -INFINITY;
        #pragma unroll
        for (int nt = 0; nt < 8; nt++) {
            float m0 = mkt[nt * 8 + 2 * qd], m1 = mkt[nt * 8 + 2 * qd + 1];
            c[nt][0] += m0; c[nt][1] += m1; c[nt][2] += m0; c[nt][3] += m1;
            rmA = fmaxf(rmA, fmaxf(c[nt][0], c[nt][1]));
            rmB = fmaxf(rmB, fmaxf(c[nt][2], c[nt][3]));
        }
        rmA = fmaxf(rmA, __shfl_xor_sync(0xffffffffu, rmA, 1));
        rmA = fmaxf(rmA, __shfl_xor_sync(0xffffffffu, rmA, 2));
        rmB = fmaxf(rmB, __shfl_xor_sync(0xffffffffu, rmB, 1));
        rmB = fmaxf(rmB, __shfl_xor_sync(0xffffffffu, rmB, 2));

        float nmA = fmaxf(m_A, rmA), nmB = fmaxf(m_B, rmB);
        float sclA = __expf(m_A - nmA), sclB = __expf(m_B - nmB);
        m_A = nmA; m_B = nmB;

        float rsA = 0.f, rsB = 0.f;
        #pragma unroll
        for (int nt = 0; nt < 8; nt++) {
            float p0 = __expf(c[nt][0] - nmA), p1 = __expf(c[nt][1] - nmA);
            float p2 = __expf(c[nt][2] - nmB), p3 = __expf(c[nt][3] - nmB);
            rsA += p0 + p1; rsB += p2 + p3;
            *(__half2*)(Ph + (r0 + g) * PP + nt * 8 + 2 * qd)     = __floats2half2_rn(p0, p1);
            *(__half2*)(Ph + (r0 + g + 8) * PP + nt * 8 + 2 * qd) = __floats2half2_rn(p2, p3);
        }
        rsA += __shfl_xor_sync(0xffffffffu, rsA, 1);
        rsA += __shfl_xor_sync(0xffffffffu, rsA, 2);
        rsB += __shfl_xor_sync(0xffffffffu, rsB, 1);
        rsB += __shfl_xor_sync(0xffffffffu, rsB, 2);
        l_A = l_A * sclA + rsA;
        l_B = l_B * sclB + rsB;

        #pragma unroll
        for (int nt2 = 0; nt2 < 16; nt2++) {
            o[nt2][0] *= sclA; o[nt2][1] *= sclA;
            o[nt2][2] *= sclB; o[nt2][3] *= sclB;
        }
        __syncwarp();

        // ---- O += P @ V : warp computes 16 x 128 ----
        #pragma unroll
        for (int ks = 0; ks < 4; ks++) {
            unsigned a0, a1, a2, a3;
            ldsm4(aP + ks * 32, a0, a1, a2, a3);
            #pragma unroll
            for (int nt2 = 0; nt2 < 16; nt2++) {
                unsigned b0, b1;
                ldsm2t(aV + kOff + ks * (16 * QP * 2) + nt2 * 16, b0, b1);
                mma16816(o[nt2][0], o[nt2][1], o[nt2][2], o[nt2][3], a0, a1, a2, a3, b0, b1);
            }
        }
        __syncthreads();
    }

    // ---- epilogue: normalize, residual, LayerNorm, store ----
    const float invA = 1.f / l_A, invB = 1.f / l_B;
    const int nA = qb + r0 + g, nB = nA + 8;

    #pragma unroll
    for (int half = 0; half < 2; half++) {
        const int n = half ? nB : nA;
        const float inv = half ? invB : invA;
        float vals[32];
        float sum = 0.f, sq = 0.f;
        #pragma unroll
        for (int nt2 = 0; nt2 < 16; nt2++) {
            #pragma unroll
            for (int j = 0; j < 2; j++) {
                int co = nt2 * 8 + 2 * qd + j;
                float val = o[nt2][2 * half + j] * inv
                          + x[((size_t)(b * CH + co)) * NTOK + n];
                vals[nt2 * 2 + j] = val;
                sum += val; sq += val * val;
            }
        }
        sum += __shfl_xor_sync(0xffffffffu, sum, 1);
        sum += __shfl_xor_sync(0xffffffffu, sum, 2);
        sq  += __shfl_xor_sync(0xffffffffu, sq, 1);
        sq  += __shfl_xor_sync(0xffffffffu, sq, 2);
        float mu   = sum * (1.f / 128.f);
        float var  = sq * (1.f / 128.f) - mu * mu;
        float rstd = rsqrtf(var + 1e-5f);
        #pragma unroll
        for (int nt2 = 0; nt2 < 16; nt2++) {
            #pragma unroll
            for (int j = 0; j < 2; j++) {
                int co = nt2 * 8 + 2 * qd + j;
                out[((size_t)(b * CH + co)) * NTOK + n] =
                    (vals[nt2 * 2 + j] - mu) * rstd * gms[co] + bts[co];
            }
        }
    }
}

// ---------------------------------------------------------------------------
extern "C" void kernel_launch(void* const* d_in, const int* in_sizes, int n_in,
                              void* d_out, int out_size)
{
    const float* prompt = (const float*)d_in[0];
    const float* x      = (const float*)d_in[1];
    const float* Wq     = (const float*)d_in[2];
    const float* bq     = (const float*)d_in[3];
    const float* Wk     = (const float*)d_in[4];
    const float* bk     = (const float*)d_in[5];
    const float* Wv     = (const float*)d_in[6];
    const float* bv     = (const float*)d_in[7];
    const float* gamma  = (const float*)d_in[8];
    const float* beta   = (const float*)d_in[9];
    const int*   mask   = (const int*)d_in[10];
    float* out = (float*)d_out;

    const int qkv_smem = (64 * 132 + 128 * 132) * (int)sizeof(float);

    cudaFuncSetAttribute(qkv_kernel,  cudaFuncAttributeMaxDynamicSharedMemorySize, qkv_smem);
    cudaFuncSetAttribute(attn_kernel, cudaFuncAttributeMaxDynamicSharedMemorySize, SMEM_TOT);

    dim3 grid_qkv(BATCH * 64, 3);
    qkv_kernel<<<grid_qkv, 256, qkv_smem>>>(prompt, x, Wq, bq, Wk, bk, Wv, bv);
    attn_kernel<<<BATCH * (NTOK / TQ), 256, SMEM_TOT>>>(x, mask, gamma, beta, out);
}

// round 5
// speedup vs baseline: 7.6080x; 1.1902x over previous
#include <cuda_runtime.h>
#include <cuda_fp16.h>
#include <math.h>

#define BATCH 4
#define CH    128
#define NTOK  4096
#define TQ    128
#define TK    64
#define QP    136   // Q/K/V smem pitch (halves); 272B stride -> conflict-free ldmatrix
#define PP    72    // P smem pitch (halves)
#define WPI   136   // qkv smem pitch

// fp16 staging buffers written by qkv kernel (Q pre-scaled by 1/sqrt(C)).
__device__ __half g_Q[BATCH * NTOK * CH];
__device__ __half g_K[BATCH * NTOK * CH];
__device__ __half g_V[BATCH * NTOK * CH];

// ---------------------------------------------------------------------------
// PTX helpers
// ---------------------------------------------------------------------------
__device__ __forceinline__ unsigned smem_u32(const void* p) {
    return (unsigned)__cvta_generic_to_shared(p);
}
__device__ __forceinline__ void cp16(unsigned dst, const void* src) {
    asm volatile("cp.async.cg.shared.global [%0], [%1], 16;\n" :: "r"(dst), "l"(src));
}
__device__ __forceinline__ void cp_commit() {
    asm volatile("cp.async.commit_group;\n");
}
template<int N> __device__ __forceinline__ void cp_wait() {
    asm volatile("cp.async.wait_group %0;\n" :: "n"(N));
}
__device__ __forceinline__ void ldsm4(unsigned addr, unsigned& a0, unsigned& a1,
                                      unsigned& a2, unsigned& a3) {
    asm volatile("ldmatrix.sync.aligned.m8n8.x4.shared.b16 {%0,%1,%2,%3}, [%4];\n"
                 : "=r"(a0), "=r"(a1), "=r"(a2), "=r"(a3) : "r"(addr));
}
__device__ __forceinline__ void ldsm4t(unsigned addr, unsigned& a0, unsigned& a1,
                                       unsigned& a2, unsigned& a3) {
    asm volatile("ldmatrix.sync.aligned.m8n8.x4.trans.shared.b16 {%0,%1,%2,%3}, [%4];\n"
                 : "=r"(a0), "=r"(a1), "=r"(a2), "=r"(a3) : "r"(addr));
}
__device__ __forceinline__ void mma16816(float& d0, float& d1, float& d2, float& d3,
                                         unsigned a0, unsigned a1, unsigned a2, unsigned a3,
                                         unsigned b0, unsigned b1) {
    asm volatile("mma.sync.aligned.m16n8k16.row.col.f32.f16.f16.f32 "
                 "{%0,%1,%2,%3}, {%4,%5,%6,%7}, {%8,%9}, {%0,%1,%2,%3};\n"
                 : "+f"(d0), "+f"(d1), "+f"(d2), "+f"(d3)
                 : "r"(a0), "r"(a1), "r"(a2), "r"(a3), "r"(b0), "r"(b1));
}

// ---------------------------------------------------------------------------
// Kernel 1: tensor-core QKV. Block = 128 tokens; computes Q,K,V projections.
// Warp = 16 tokens x 128 outputs. fp32 gmem -> fp16 smem -> mma (fp32 accum).
// ---------------------------------------------------------------------------
__global__ __launch_bounds__(256, 1)
void qkv_kernel(const float* __restrict__ prompt, const float* __restrict__ x,
                const float* __restrict__ Wq, const float* __restrict__ bq,
                const float* __restrict__ Wk, const float* __restrict__ bk,
                const float* __restrict__ Wv, const float* __restrict__ bv)
{
    extern __shared__ char smraw[];
    __half* Xp  = (__half*)smraw;           // prompt tile 128x136
    __half* Xx  = Xp  + 128 * WPI;          // x tile
    __half* Wqs = Xx  + 128 * WPI;          // 128x136 each
    __half* Wks = Wqs + 128 * WPI;
    __half* Wvs = Wks + 128 * WPI;
    float*  bqs = (float*)(Wvs + 128 * WPI);
    float*  bks = bqs + 128;
    float*  bvs = bks + 128;

    const int b  = blockIdx.x >> 5;
    const int nb = (blockIdx.x & 31) * 128;
    const int tid = threadIdx.x;

    // Input tiles, transposed (c,n)->(t,c), fp32->fp16.
    for (int idx = tid; idx < 128 * 128; idx += 256) {
        int c = idx >> 7, t = idx & 127;
        size_t gofs = ((size_t)b * CH + c) * NTOK + nb + t;
        Xp[t * WPI + c] = __float2half(prompt[gofs]);
        Xx[t * WPI + c] = __float2half(x[gofs]);
    }
    // Weights (already k-contiguous for the B operand).
    for (int idx = tid; idx < 128 * 128; idx += 256) {
        int co = idx >> 7, c = idx & 127;
        Wqs[co * WPI + c] = __float2half(Wq[idx]);
        Wks[co * WPI + c] = __float2half(Wk[idx]);
        Wvs[co * WPI + c] = __float2half(Wv[idx]);
    }
    if (tid < 128) { bqs[tid] = bq[tid]; bks[tid] = bk[tid]; bvs[tid] = bv[tid]; }
    __syncthreads();

    const int lane = tid & 31, wid = tid >> 5;
    const int r0 = wid * 16;
    const int g = lane >> 2, qd = lane & 3;

    const unsigned aXp = smem_u32(Xp) + ((r0 + (lane & 15)) * WPI + (lane >> 4) * 8) * 2;
    const unsigned aXx = aXp + (unsigned)(128 * WPI * 2);
    const unsigned w4 = (((lane >> 4) * 8 + (lane & 7)) * WPI + ((lane >> 3) & 1) * 8) * 2;

    #pragma unroll 1
    for (int p = 0; p < 3; p++) {
        const unsigned aA = (p == 0) ? aXp : aXx;
        const unsigned aW = smem_u32(p == 0 ? Wqs : (p == 1 ? Wks : Wvs)) + w4;
        const float* bias = (p == 0) ? bqs : (p == 1) ? bks : bvs;
        __half* outg      = (p == 0) ? g_Q : (p == 1) ? g_K : g_V;
        const float os    = (p == 0) ? 0.0883883476483184f : 1.0f;

        float c[16][4];
        #pragma unroll
        for (int nt = 0; nt < 16; nt++) { c[nt][0] = c[nt][1] = c[nt][2] = c[nt][3] = 0.f; }

        #pragma unroll
        for (int ks = 0; ks < 8; ks++) {
            unsigned a0, a1, a2, a3;
            ldsm4(aA + ks * 32, a0, a1, a2, a3);
            #pragma unroll
            for (int ntp = 0; ntp < 8; ntp++) {
                unsigned b0, b1, b2, b3;
                ldsm4(aW + ntp * (16 * WPI * 2) + ks * 32, b0, b1, b2, b3);
                mma16816(c[2*ntp][0], c[2*ntp][1], c[2*ntp][2], c[2*ntp][3],
                         a0, a1, a2, a3, b0, b1);
                mma16816(c[2*ntp+1][0], c[2*ntp+1][1], c[2*ntp+1][2], c[2*ntp+1][3],
                         a0, a1, a2, a3, b2, b3);
            }
        }

        __half* row0 = outg + (size_t)(b * NTOK + nb + r0 + g) * CH;
        __half* row1 = row0 + 8 * CH;
        #pragma unroll
        for (int nt = 0; nt < 16; nt++) {
            int co = nt * 8 + 2 * qd;
            float b0v = bias[co], b1v = bias[co + 1];
            *(__half2*)(row0 + co) = __floats2half2_rn((c[nt][0] + b0v) * os, (c[nt][1] + b1v) * os);
            *(__half2*)(row1 + co) = __floats2half2_rn((c[nt][2] + b0v) * os, (c[nt][3] + b1v) * os);
        }
    }
}

// ---------------------------------------------------------------------------
// Kernel 2: fp16 tensor-core flash attention + residual + LayerNorm.
// Block = 128 queries, 8 warps; warp = 16 rows x 64 keys. x4 ldmatrix for K/V.
// ---------------------------------------------------------------------------
#define SMEM_Q   0
#define SMEM_K   34816            // 2 bufs x 64*136*2
#define SMEM_V   69632
#define SMEM_P   104448           // 128*72*2
#define SMEM_MK  122880           // 4096 floats
#define SMEM_GB  139264
#define SMEM_TOT 140288
#define KVBUF    (TK * QP * 2)

__global__ __launch_bounds__(256, 1)
void attn_kernel(const float* __restrict__ x, const int* __restrict__ mask,
                 const float* __restrict__ gamma, const float* __restrict__ beta,
                 float* __restrict__ out)
{
    extern __shared__ char smraw[];
    char* sm = smraw;
    __half* Qh  = (__half*)(sm + SMEM_Q);
    __half* Kh  = (__half*)(sm + SMEM_K);
    __half* Vh  = (__half*)(sm + SMEM_V);
    __half* Ph  = (__half*)(sm + SMEM_P);
    float*  mk  = (float*)(sm + SMEM_MK);
    float*  gms = (float*)(sm + SMEM_GB);
    float*  bts = gms + 128;

    const int tid = threadIdx.x, lane = tid & 31, wid = tid >> 5;
    const int b  = blockIdx.x >> 5;
    const int qb = (blockIdx.x & 31) * TQ;
    const int r0 = wid * 16;
    const int g  = lane >> 2, qd = lane & 3;

    for (int i = tid; i < 2048; i += 256) {
        int row = i >> 4, c8 = (i & 15) * 8;
        *(uint4*)(Qh + row * QP + c8) =
            *(const uint4*)(g_Q + ((size_t)(b * NTOK + qb + row)) * CH + c8);
    }
    for (int i = tid; i < NTOK; i += 256)
        mk[i] = (mask[b * NTOK + i] > 0) ? 0.0f : -1e30f;
    if (tid < 128) { gms[tid] = gamma[tid]; bts[tid] = beta[tid]; }

    {
        const __half* Ksrc = g_K + ((size_t)(b * NTOK)) * CH;
        const __half* Vsrc = g_V + ((size_t)(b * NTOK)) * CH;
        for (int i = tid; i < 1024; i += 256) {
            int row = i >> 4, c8 = (i & 15) * 8;
            cp16(smem_u32(Kh + row * QP + c8), Ksrc + row * CH + c8);
            cp16(smem_u32(Vh + row * QP + c8), Vsrc + row * CH + c8);
        }
        cp_commit();
    }

    // ldmatrix base addresses
    const unsigned aQ  = smem_u32(Qh) + ((r0 + (lane & 15)) * QP + ((lane >> 4) * 8)) * 2;
    const unsigned aP  = smem_u32(Ph) + ((r0 + (lane & 15)) * PP + ((lane >> 4) * 8)) * 2;
    // x4 K: groups: {nt rows k0, nt rows k8, nt+1 rows k0, nt+1 rows k8}
    const unsigned aK4 = smem_u32(Kh) + (((lane >> 4) * 8 + (lane & 7)) * QP + ((lane >> 3) & 1) * 8) * 2;
    // x4 V (trans): 16 key rows, channel col split by lane>>4
    const unsigned aV4 = smem_u32(Vh) + ((lane & 15) * QP) * 2 + (lane >> 4) * 16;

    float m_A = -INFINITY, m_B = -INFINITY, l_A = 0.f, l_B = 0.f;
    float o[16][4];
    #pragma unroll
    for (int i = 0; i < 16; i++) { o[i][0] = o[i][1] = o[i][2] = o[i][3] = 0.f; }

    for (int kt = 0; kt < NTOK / TK; kt++) {
        if (kt < NTOK / TK - 1) {
            int nbuf = (kt + 1) & 1;
            const __half* Ksrc = g_K + ((size_t)(b * NTOK + (kt + 1) * TK)) * CH;
            const __half* Vsrc = g_V + ((size_t)(b * NTOK + (kt + 1) * TK)) * CH;
            for (int i = tid; i < 1024; i += 256) {
                int row = i >> 4, c8 = (i & 15) * 8;
                cp16(smem_u32(Kh + nbuf * (TK * QP) + row * QP + c8), Ksrc + row * CH + c8);
                cp16(smem_u32(Vh + nbuf * (TK * QP) + row * QP + c8), Vsrc + row * CH + c8);
            }
            cp_commit();
            cp_wait<1>();
        } else {
            cp_wait<0>();
        }
        __syncthreads();

        const unsigned kOff = (kt & 1) * KVBUF;

        // ---- scores S = Q K^T : 16 x 64 per warp (x4 B loads) ----
        float c[8][4];
        #pragma unroll
        for (int nt = 0; nt < 8; nt++) { c[nt][0] = c[nt][1] = c[nt][2] = c[nt][3] = 0.f; }

        #pragma unroll
        for (int ks = 0; ks < 8; ks++) {
            unsigned a0, a1, a2, a3;
            ldsm4(aQ + ks * 32, a0, a1, a2, a3);
            #pragma unroll
            for (int ntp = 0; ntp < 4; ntp++) {
                unsigned b0, b1, b2, b3;
                ldsm4(aK4 + kOff + ntp * (16 * QP * 2) + ks * 32, b0, b1, b2, b3);
                mma16816(c[2*ntp][0], c[2*ntp][1], c[2*ntp][2], c[2*ntp][3],
                         a0, a1, a2, a3, b0, b1);
                mma16816(c[2*ntp+1][0], c[2*ntp+1][1], c[2*ntp+1][2], c[2*ntp+1][3],
                         a0, a1, a2, a3, b2, b3);
            }
        }

        // ---- mask + warp-local online softmax ----
        const float* mkt = mk + kt * TK;
        float rmA = -INFINITY, rmB = -INFINITY;
        #pragma unroll
        for (int nt = 0; nt < 8; nt++) {
            float m0 = mkt[nt * 8 + 2 * qd], m1 = mkt[nt * 8 + 2 * qd + 1];
            c[nt][0] += m0; c[nt][1] += m1; c[nt][2] += m0; c[nt][3] += m1;
            rmA = fmaxf(rmA, fmaxf(c[nt][0], c[nt][1]));
            rmB = fmaxf(rmB, fmaxf(c[nt][2], c[nt][3]));
        }
        rmA = fmaxf(rmA, __shfl_xor_sync(0xffffffffu, rmA, 1));
        rmA = fmaxf(rmA, __shfl_xor_sync(0xffffffffu, rmA, 2));
        rmB = fmaxf(rmB, __shfl_xor_sync(0xffffffffu, rmB, 1));
        rmB = fmaxf(rmB, __shfl_xor_sync(0xffffffffu, rmB, 2));

        float nmA = fmaxf(m_A, rmA), nmB = fmaxf(m_B, rmB);
        float sclA = __expf(m_A - nmA), sclB = __expf(m_B - nmB);
        m_A = nmA; m_B = nmB;

        float rsA = 0.f, rsB = 0.f;
        #pragma unroll
        for (int nt = 0; nt < 8; nt++) {
            float p0 = __expf(c[nt][0] - nmA), p1 = __expf(c[nt][1] - nmA);
            float p2 = __expf(c[nt][2] - nmB), p3 = __expf(c[nt][3] - nmB);
            rsA += p0 + p1; rsB += p2 + p3;
            *(__half2*)(Ph + (r0 + g) * PP + nt * 8 + 2 * qd)     = __floats2half2_rn(p0, p1);
            *(__half2*)(Ph + (r0 + g + 8) * PP + nt * 8 + 2 * qd) = __floats2half2_rn(p2, p3);
        }
        rsA += __shfl_xor_sync(0xffffffffu, rsA, 1);
        rsA += __shfl_xor_sync(0xffffffffu, rsA, 2);
        rsB += __shfl_xor_sync(0xffffffffu, rsB, 1);
        rsB += __shfl_xor_sync(0xffffffffu, rsB, 2);
        l_A = l_A * sclA + rsA;
        l_B = l_B * sclB + rsB;

        #pragma unroll
        for (int nt2 = 0; nt2 < 16; nt2++) {
            o[nt2][0] *= sclA; o[nt2][1] *= sclA;
            o[nt2][2] *= sclB; o[nt2][3] *= sclB;
        }
        __syncwarp();

        // ---- O += P @ V : 16 x 128 per warp (x4 trans B loads) ----
        #pragma unroll
        for (int ks = 0; ks < 4; ks++) {
            unsigned a0, a1, a2, a3;
            ldsm4(aP + ks * 32, a0, a1, a2, a3);
            #pragma unroll
            for (int ntp = 0; ntp < 8; ntp++) {
                unsigned b0, b1, b2, b3;
                ldsm4t(aV4 + kOff + ks * (16 * QP * 2) + ntp * 32, b0, b1, b2, b3);
                mma16816(o[2*ntp][0], o[2*ntp][1], o[2*ntp][2], o[2*ntp][3],
                         a0, a1, a2, a3, b0, b1);
                mma16816(o[2*ntp+1][0], o[2*ntp+1][1], o[2*ntp+1][2], o[2*ntp+1][3],
                         a0, a1, a2, a3, b2, b3);
            }
        }
        __syncthreads();
    }

    // ---- epilogue: normalize, residual, LayerNorm, store ----
    const float invA = 1.f / l_A, invB = 1.f / l_B;
    const int nA = qb + r0 + g, nB = nA + 8;

    #pragma unroll
    for (int half = 0; half < 2; half++) {
        const int n = half ? nB : nA;
        const float inv = half ? invB : invA;
        float vals[32];
        float sum = 0.f, sq = 0.f;
        #pragma unroll
        for (int nt2 = 0; nt2 < 16; nt2++) {
            #pragma unroll
            for (int j = 0; j < 2; j++) {
                int co = nt2 * 8 + 2 * qd + j;
                float val = o[nt2][2 * half + j] * inv
                          + x[((size_t)(b * CH + co)) * NTOK + n];
                vals[nt2 * 2 + j] = val;
                sum += val; sq += val * val;
            }
        }
        sum += __shfl_xor_sync(0xffffffffu, sum, 1);
        sum += __shfl_xor_sync(0xffffffffu, sum, 2);
        sq  += __shfl_xor_sync(0xffffffffu, sq, 1);
        sq  += __shfl_xor_sync(0xffffffffu, sq, 2);
        float mu   = sum * (1.f / 128.f);
        float var  = sq * (1.f / 128.f) - mu * mu;
        float rstd = rsqrtf(var + 1e-5f);
        #pragma unroll
        for (int nt2 = 0; nt2 < 16; nt2++) {
            #pragma unroll
            for (int j = 0; j < 2; j++) {
                int co = nt2 * 8 + 2 * qd + j;
                out[((size_t)(b * CH + co)) * NTOK + n] =
                    (vals[nt2 * 2 + j] - mu) * rstd * gms[co] + bts[co];
            }
        }
    }
}

// ---------------------------------------------------------------------------
extern "C" void kernel_launch(void* const* d_in, const int* in_sizes, int n_in,
                              void* d_out, int out_size)
{
    const float* prompt = (const float*)d_in[0];
    const float* x      = (const float*)d_in[1];
    const float* Wq     = (const float*)d_in[2];
    const float* bq     = (const float*)d_in[3];
    const float* Wk     = (const float*)d_in[4];
    const float* bk     = (const float*)d_in[5];
    const float* Wv     = (const float*)d_in[6];
    const float* bv     = (const float*)d_in[7];
    const float* gamma  = (const float*)d_in[8];
    const float* beta   = (const float*)d_in[9];
    const int*   mask   = (const int*)d_in[10];
    float* out = (float*)d_out;

    const int qkv_smem = (5 * 128 * WPI) * 2 + 3 * 128 * (int)sizeof(float); // 175616

    cudaFuncSetAttribute(qkv_kernel,  cudaFuncAttributeMaxDynamicSharedMemorySize, qkv_smem);
    cudaFuncSetAttribute(attn_kernel, cudaFuncAttributeMaxDynamicSharedMemorySize, SMEM_TOT);

    qkv_kernel<<<BATCH * 32, 256, qkv_smem>>>(prompt, x, Wq, bq, Wk, bk, Wv, bv);
    attn_kernel<<<BATCH * (NTOK / TQ), 256, SMEM_TOT>>>(x, mask, gamma, beta, out);
}